// round 15
// baseline (speedup 1.0000x reference)
#include <cuda_runtime.h>
#include <cuda_fp16.h>
#include <mma.h>
#include <cstdint>

using namespace nvcuda;

// Problem constants
#define BB 4
#define NN 4096
#define DIMM 1024
#define HH 16
#define HDD 64
#define MM (BB * NN)           // 16384 rows
#define KVC 16                 // kv partial chunks (256 rows each)

// ---------------- scratch (device globals; no allocation allowed) ----------
__device__ __half g_hq[(size_t)MM * DIMM];
__device__ __half g_hk[(size_t)MM * DIMM];
__device__ __half g_hv[(size_t)MM * DIMM];
__device__ __half g_Q16[(size_t)MM * DIMM];
__device__ __half g_K16[(size_t)MM * DIMM];
__device__ __half g_V16[(size_t)MM * DIMM];
__device__ __half g_hA[(size_t)MM * DIMM];
__device__ __half g_Wh[4 * DIMM * DIMM];
__device__ float  g_kvp[(size_t)KVC * BB * HH * HDD * HDD];
__device__ float  g_ksp[(size_t)KVC * BB * HH * HDD];
__device__ __half g_kv16[BB * HH * HDD * HDD];
__device__ float  g_ksum[BB * HH * HDD];

__device__ __forceinline__ void cp_async16(void* smem_ptr, const void* gmem_ptr) {
    unsigned int s = (unsigned int)__cvta_generic_to_shared(smem_ptr);
    asm volatile("cp.async.cg.shared.global [%0], [%1], 16;\n" :: "r"(s), "l"(gmem_ptr));
}

// ---------------- fused fp32 -> fp16 conversion (RN) ----------------
// grid.y 0..2: activations (q,k,v). grid.y 3: all four weight matrices.
__global__ void cvt_all(const float* __restrict__ A0, const float* __restrict__ A1,
                        const float* __restrict__ A2,
                        const float* __restrict__ W0, const float* __restrict__ W1,
                        const float* __restrict__ W2, const float* __restrict__ W3,
                        __half* __restrict__ D0, __half* __restrict__ D1,
                        __half* __restrict__ D2, __half* __restrict__ Wh) {
    const int y = blockIdx.y;
    int i = blockIdx.x * blockDim.x + threadIdx.x;
    if (y < 3) {
        const float* srcs[3] = {A0, A1, A2};
        __half* dsts[3] = {D0, D1, D2};
        if (i < (MM * DIMM) / 4) {
            float4 v = ((const float4*)srcs[y])[i];
            __half2* d = (__half2*)dsts[y];
            d[2 * i + 0] = __floats2half2_rn(v.x, v.y);
            d[2 * i + 1] = __floats2half2_rn(v.z, v.w);
        }
    } else {
        // 4 x 1024 x 1024 floats = 1048576 float4 total
        if (i < (4 * DIMM * DIMM) / 4) {
            const float* ws[4] = {W0, W1, W2, W3};
            const int m = i >> 18;            // 262144 float4 per matrix
            const int j = i & 262143;
            float4 v = ((const float4*)ws[m])[j];
            __half2* d = (__half2*)(Wh + (size_t)m * DIMM * DIMM);
            d[2 * j + 0] = __floats2half2_rn(v.x, v.y);
            d[2 * j + 1] = __floats2half2_rn(v.z, v.w);
        }
    }
}

// ==== fp16 GEMM (R12 shape): 128x128 block, 8 warps, 32x64 tile, KC=64 ====
#define KC 64
#define HPAD 72
#define HTILE (128 * HPAD)
#define HSTAGE (2 * HTILE)
#define GEMM_DSMEM (2 * HSTAGE * 2)        // 73728 bytes

extern __shared__ __align__(16) __half dsm_h[];

struct GemmCore {
    wmma::fragment<wmma::accumulator, 16, 16, 16, float> acc[2][4];
    int t, w, wm, wn;

    __device__ __forceinline__ void init(int tid) {
        t = tid; w = t >> 5; wm = w >> 1; wn = w & 1;
#pragma unroll
        for (int i = 0; i < 2; i++)
#pragma unroll
            for (int j = 0; j < 4; j++)
                wmma::fill_fragment(acc[i][j], 0.0f);
    }

    __device__ __forceinline__ void load_chunk(const __half* Abase, const __half* Bbase,
                                               int kc, int s) {
        __half* As = dsm_h + s * HSTAGE;
        __half* Bs = As + HTILE;
        const int k0 = kc * KC;
#pragma unroll
        for (int j = 0; j < 4; j++) {
            int u = t + j * 256;
            int row = u >> 3;
            int c8 = (u & 7) * 8;
            cp_async16(&As[row * HPAD + c8], Abase + (size_t)row * DIMM + k0 + c8);
            cp_async16(&Bs[row * HPAD + c8], Bbase + (size_t)row * DIMM + k0 + c8);
        }
    }

    __device__ __forceinline__ void mainloop(const __half* Abase, const __half* Bbase) {
        load_chunk(Abase, Bbase, 0, 0);
        asm volatile("cp.async.commit_group;\n");
        const int NCH = DIMM / KC;   // 16
        for (int i = 0; i < NCH; i++) {
            const int s = i & 1;
            if (i + 1 < NCH) {
                load_chunk(Abase, Bbase, i + 1, s ^ 1);
                asm volatile("cp.async.commit_group;\n");
                asm volatile("cp.async.wait_group 1;\n");
            } else {
                asm volatile("cp.async.wait_group 0;\n");
            }
            __syncthreads();

            const __half* As = dsm_h + s * HSTAGE;
            const __half* Bs = As + HTILE;
#pragma unroll
            for (int kk = 0; kk < KC; kk += 16) {
                wmma::fragment<wmma::matrix_a, 16, 16, 16, __half, wmma::row_major> af[2];
                wmma::fragment<wmma::matrix_b, 16, 16, 16, __half, wmma::col_major> bf[4];
#pragma unroll
                for (int x = 0; x < 2; x++)
                    wmma::load_matrix_sync(af[x], As + (wm * 32 + x * 16) * HPAD + kk, HPAD);
#pragma unroll
                for (int y = 0; y < 4; y++)
                    wmma::load_matrix_sync(bf[y], Bs + (wn * 64 + y * 16) * HPAD + kk, HPAD);
#pragma unroll
                for (int x = 0; x < 2; x++)
#pragma unroll
                    for (int y = 0; y < 4; y++)
                        wmma::mma_sync(acc[x][y], af[x], bf[y], acc[x][y]);
            }
            __syncthreads();
        }
    }

    // single-pass epilogue: full 128x132 fp32 tile in smem (67.6KB <= 72KB)
    __device__ __forceinline__ void epilogue(const float* bias,
                                             float* Cf, __half* Ch, int do_relu,
                                             int m0, int n0) {
        float* Ct = (float*)dsm_h;
#pragma unroll
        for (int x = 0; x < 2; x++)
#pragma unroll
            for (int y = 0; y < 4; y++)
                wmma::store_matrix_sync(Ct + (wm * 32 + x * 16) * 132 + wn * 64 + y * 16,
                                        acc[x][y], 132, wmma::mem_row_major);
        __syncthreads();
        // 128x128 floats = 4096 float4, 16 per thread
#pragma unroll
        for (int i = 0; i < 16; i++) {
            int u = t + i * 256;
            int r = u >> 5;
            int c = (u & 31) * 4;
            int row = m0 + r;
            float4 v = *(float4*)(Ct + r * 132 + c);
            v.x += bias[n0 + c + 0];
            v.y += bias[n0 + c + 1];
            v.z += bias[n0 + c + 2];
            v.w += bias[n0 + c + 3];
            if (do_relu) {
                v.x = fmaxf(v.x, 0.0f); v.y = fmaxf(v.y, 0.0f);
                v.z = fmaxf(v.z, 0.0f); v.w = fmaxf(v.w, 0.0f);
            }
            if (Ch != nullptr) {
                __half2* p = (__half2*)(Ch + (size_t)row * DIMM + n0 + c);
                p[0] = __floats2half2_rn(v.x, v.y);
                p[1] = __floats2half2_rn(v.z, v.w);
            } else {
                *(float4*)(Cf + (size_t)row * DIMM + n0 + c) = v;
            }
        }
    }
};

__global__ void __launch_bounds__(256, 2)
gemm_qkv(const __half* __restrict__ hq, const __half* __restrict__ hk,
         const __half* __restrict__ hv, const __half* __restrict__ Wh,
         const float* __restrict__ bq, const float* __restrict__ bk,
         const float* __restrict__ bv,
         __half* __restrict__ Q16, __half* __restrict__ K16, __half* __restrict__ V16) {
    const int z = blockIdx.z;
    const __half* A = (z == 0) ? hq : (z == 1) ? hk : hv;
    const __half* W = Wh + (size_t)z * DIMM * DIMM;
    const float* bias = (z == 0) ? bq : (z == 1) ? bk : bv;
    __half* out = (z == 0) ? Q16 : (z == 1) ? K16 : V16;
    const int do_relu = (z < 2);

    GemmCore g;
    g.init(threadIdx.x);
    const int n0 = blockIdx.x * 128;
    const int m0 = blockIdx.y * 128;
    g.mainloop(A + (size_t)m0 * DIMM, W + (size_t)n0 * DIMM);
    g.epilogue(bias, nullptr, out, do_relu, m0, n0);
}

__global__ void __launch_bounds__(256, 2)
gemm_one(const __half* __restrict__ A, const __half* __restrict__ W,
         const float* __restrict__ bias, float* __restrict__ Cf) {
    GemmCore g;
    g.init(threadIdx.x);
    const int n0 = blockIdx.x * 128;
    const int m0 = blockIdx.y * 128;
    g.mainloop(A + (size_t)m0 * DIMM, W + (size_t)n0 * DIMM);
    g.epilogue(bias, Cf, nullptr, 0, m0, n0);
}

// ---- kv partials via fp16 WMMA; key-padding mask applied HERE -------------
// kvp[c][bh] = (masked K_c)^T @ V_c (64x64x256); ksp likewise from masked K.
#define KVPAD 72
__global__ void __launch_bounds__(128)
kv_h(const __half* __restrict__ K, const __half* __restrict__ V,
     const int* __restrict__ mask,
     float* __restrict__ kvp, float* __restrict__ ksp) {
    __shared__ __align__(16) __half Ks[128][KVPAD];
    __shared__ __align__(16) __half Vs[128][KVPAD];
    __shared__ float ksb[128];

    const int bh = blockIdx.y;
    const int b = bh >> 4, h = bh & 15;
    const int chunk = blockIdx.x;
    const int t = threadIdx.x;
    const int w = t >> 5;
    const int d0 = w * 16;
    const int dcol = t & 63, rhalf = t >> 6;

    wmma::fragment<wmma::accumulator, 16, 16, 16, float> acc[4];
#pragma unroll
    for (int e = 0; e < 4; e++) wmma::fill_fragment(acc[e], 0.0f);
    float ksacc = 0.0f;

#pragma unroll
    for (int sub = 0; sub < 2; sub++) {
        const int n0 = chunk * 256 + sub * 128;
#pragma unroll
        for (int j = 0; j < 8; j++) {
            int u = t + j * 128;
            int row = u >> 3;
            int c8 = (u & 7) * 8;
            const size_t goff = (size_t)(b * NN + n0 + row) * DIMM + h * HDD + c8;
            cp_async16(&Ks[row][c8], K + goff);
            cp_async16(&Vs[row][c8], V + goff);
        }
        asm volatile("cp.async.commit_group;\n");
        asm volatile("cp.async.wait_group 0;\n");
        __syncthreads();

        // key padding: zero K row t if masked (thread t owns row t)
        if (mask[b * NN + n0 + t] != 0) {
            uint4 z = {0, 0, 0, 0};
#pragma unroll
            for (int c16 = 0; c16 < 8; c16++)
                *(uint4*)&Ks[t][c16 * 8] = z;
        }
        __syncthreads();

#pragma unroll 16
        for (int r = rhalf * 64; r < rhalf * 64 + 64; r++)
            ksacc += __half2float(Ks[r][dcol]);

#pragma unroll
        for (int ns = 0; ns < 128; ns += 16) {
            wmma::fragment<wmma::matrix_a, 16, 16, 16, __half, wmma::col_major> a;
            wmma::load_matrix_sync(a, &Ks[ns][d0], KVPAD);
#pragma unroll
            for (int e = 0; e < 4; e++) {
                wmma::fragment<wmma::matrix_b, 16, 16, 16, __half, wmma::row_major> bfr;
                wmma::load_matrix_sync(bfr, &Vs[ns][e * 16], KVPAD);
                wmma::mma_sync(acc[e], a, bfr, acc[e]);
            }
        }
        __syncthreads();
    }

    float* dst = kvp + ((size_t)chunk * 64 + bh) * (HDD * HDD);
#pragma unroll
    for (int e = 0; e < 4; e++)
        wmma::store_matrix_sync(dst + d0 * 64 + e * 16, acc[e], 64, wmma::mem_row_major);

    ksb[t] = ksacc;
    __syncthreads();
    if (t < 64) ksp[((size_t)chunk * 64 + bh) * HDD + t] = ksb[t] + ksb[t + 64];
}

// ---- reduce partials: kv -> fp16, ksum -> fp32 ----
__global__ void __launch_bounds__(256)
reduce_kv(const float* __restrict__ kvp, const float* __restrict__ ksp,
          __half* __restrict__ kv16, float* __restrict__ ksum) {
    const int bh = blockIdx.x;
    const int t = threadIdx.x;
    for (int i = t; i < HDD * HDD; i += 256) {
        float s = 0.0f;
#pragma unroll
        for (int c = 0; c < KVC; c++)
            s += kvp[((size_t)c * 64 + bh) * (HDD * HDD) + i];
        kv16[(size_t)bh * (HDD * HDD) + i] = __float2half_rn(s);
    }
    if (t < 64) {
        float s = 0.0f;
#pragma unroll
        for (int c = 0; c < KVC; c++)
            s += ksp[((size_t)c * 64 + bh) * HDD + t];
        ksum[bh * HDD + t] = s;
    }
}

// ---- WMMA attn: out = (Q @ kv) / (Q.ksum + eps), fp16 in/out --------------
#define APAD 72
#define ATTN_OFF_KV 18432                       // after Q tile (128*72*2)
#define ATTN_OFF_KSS 34816                      // after C tile (128*68*4)
#define ATTN_OFF_DEN 35072
#define ATTN_DSMEM 35584

__global__ void __launch_bounds__(128)
attn_h(const __half* __restrict__ Q, const __half* __restrict__ kv16,
       const float* __restrict__ ksum, __half* __restrict__ out) {
    char* dyn = (char*)dsm_h;
    __half* Qs = (__half*)dyn;                      // [128][APAD]
    __half* KVs = (__half*)(dyn + ATTN_OFF_KV);     // [64][APAD]
    float* Cs = (float*)dyn;                        // [128][68] (reuse after MMA)
    float* kss = (float*)(dyn + ATTN_OFF_KSS);      // [64]
    float* dn = (float*)(dyn + ATTN_OFF_DEN);       // [128]

    const int bh = blockIdx.y;
    const int b = bh >> 4, h = bh & 15;
    const int nbase = blockIdx.x * 128;
    const int t = threadIdx.x;
    const int w = t >> 5;

#pragma unroll
    for (int j = 0; j < 8; j++) {
        int u = t + j * 128;
        int row = u >> 3;
        int c8 = (u & 7) * 8;
        cp_async16(&Qs[row * APAD + c8],
                   Q + (size_t)(b * NN + nbase + row) * DIMM + h * HDD + c8);
    }
#pragma unroll
    for (int j = 0; j < 4; j++) {
        int u = t + j * 128;
        int row = u >> 3;
        int c8 = (u & 7) * 8;
        cp_async16(&KVs[row * APAD + c8], kv16 + (size_t)bh * 4096 + row * 64 + c8);
    }
    if (t < 64) kss[t] = ksum[bh * 64 + t];
    asm volatile("cp.async.commit_group;\n");
    asm volatile("cp.async.wait_group 0;\n");
    __syncthreads();

    {
        float p = 0.0f;
#pragma unroll 16
        for (int d = 0; d < 64; d++)
            p += __half2float(Qs[t * APAD + d]) * kss[d];
        dn[t] = 1.0f / (p + 1e-6f);
    }

    wmma::fragment<wmma::accumulator, 16, 16, 16, float> acc[2][4];
#pragma unroll
    for (int x = 0; x < 2; x++)
#pragma unroll
        for (int y = 0; y < 4; y++)
            wmma::fill_fragment(acc[x][y], 0.0f);
#pragma unroll
    for (int k = 0; k < 64; k += 16) {
        wmma::fragment<wmma::matrix_a, 16, 16, 16, __half, wmma::row_major> af[2];
        wmma::fragment<wmma::matrix_b, 16, 16, 16, __half, wmma::row_major> bf[4];
#pragma unroll
        for (int x = 0; x < 2; x++)
            wmma::load_matrix_sync(af[x], Qs + (w * 32 + x * 16) * APAD + k, APAD);
#pragma unroll
        for (int y = 0; y < 4; y++)
            wmma::load_matrix_sync(bf[y], KVs + k * APAD + y * 16, APAD);
#pragma unroll
        for (int x = 0; x < 2; x++)
#pragma unroll
            for (int y = 0; y < 4; y++)
                wmma::mma_sync(acc[x][y], af[x], bf[y], acc[x][y]);
    }
    __syncthreads();

#pragma unroll
    for (int x = 0; x < 2; x++)
#pragma unroll
        for (int y = 0; y < 4; y++)
            wmma::store_matrix_sync(Cs + (w * 32 + x * 16) * 68 + y * 16,
                                    acc[x][y], 68, wmma::mem_row_major);
    __syncthreads();

#pragma unroll
    for (int i = 0; i < 32; i++) {
        int u = t + i * 128;
        int row = u >> 5;
        int e2 = (u & 31) * 2;
        float sc = dn[row];
        __half2 hv2 = __floats2half2_rn(Cs[row * 68 + e2] * sc, Cs[row * 68 + e2 + 1] * sc);
        *(__half2*)(out + (size_t)(b * NN + nbase + row) * DIMM + h * HDD + e2) = hv2;
    }
}

// ---------------- launch ----------------
extern "C" void kernel_launch(void* const* d_in, const int* in_sizes, int n_in,
                              void* d_out, int out_size) {
    const float* query = (const float*)d_in[0];
    const float* key   = (const float*)d_in[1];
    const float* value = (const float*)d_in[2];
    const float* Wq = (const float*)d_in[3];
    const float* bq = (const float*)d_in[4];
    const float* Wk = (const float*)d_in[5];
    const float* bk = (const float*)d_in[6];
    const float* Wv = (const float*)d_in[7];
    const float* bv = (const float*)d_in[8];
    const float* Wo = (const float*)d_in[9];
    const float* bo = (const float*)d_in[10];
    const int* mask = (const int*)d_in[11];

    float *KVPp, *KSPp, *KSp;
    __half *hq, *hk, *hv, *Q16, *K16, *V16, *hA, *Wh, *KV16;
    cudaGetSymbolAddress((void**)&hq, g_hq);
    cudaGetSymbolAddress((void**)&hk, g_hk);
    cudaGetSymbolAddress((void**)&hv, g_hv);
    cudaGetSymbolAddress((void**)&Q16, g_Q16);
    cudaGetSymbolAddress((void**)&K16, g_K16);
    cudaGetSymbolAddress((void**)&V16, g_V16);
    cudaGetSymbolAddress((void**)&hA, g_hA);
    cudaGetSymbolAddress((void**)&Wh, g_Wh);
    cudaGetSymbolAddress((void**)&KVPp, g_kvp);
    cudaGetSymbolAddress((void**)&KSPp, g_ksp);
    cudaGetSymbolAddress((void**)&KV16, g_kv16);
    cudaGetSymbolAddress((void**)&KSp, g_ksum);

    cudaFuncSetAttribute(gemm_qkv, cudaFuncAttributeMaxDynamicSharedMemorySize, GEMM_DSMEM);
    cudaFuncSetAttribute(gemm_one, cudaFuncAttributeMaxDynamicSharedMemorySize, GEMM_DSMEM);

    dim3 ggrid3(DIMM / 128, MM / 128, 3);   // (8, 128, 3)
    dim3 ggrid(DIMM / 128, MM / 128);

    // 1: fused conversion (acts + weights)
    cvt_all<<<dim3(16384, 4), 256>>>(query, key, value, Wq, Wk, Wv, Wo,
                                     hq, hk, hv, Wh);
    // 2: merged Q/K/V projections (mask removed from epilogue)
    gemm_qkv<<<ggrid3, 256, GEMM_DSMEM>>>(hq, hk, hv, Wh, bq, bk, bv, Q16, K16, V16);
    // 3-4: kv (with mask) + reduce
    kv_h<<<dim3(KVC, 64), 128>>>(K16, V16, mask, KVPp, KSPp);
    reduce_kv<<<64, 256>>>(KVPp, KSPp, KV16, KSp);
    // 5: WMMA attention
    attn_h<<<dim3(NN / 128, 64), 128, ATTN_DSMEM>>>(Q16, KV16, KSp, hA);
    // 6: output projection
    gemm_one<<<ggrid, 256, GEMM_DSMEM>>>(hA, Wh + 3 * (size_t)DIMM * DIMM, bo, (float*)d_out);
}

// round 16
// speedup vs baseline: 1.0115x; 1.0115x over previous
#include <cuda_runtime.h>
#include <cuda_fp16.h>
#include <mma.h>
#include <cstdint>

using namespace nvcuda;

// Problem constants
#define BB 4
#define NN 4096
#define DIMM 1024
#define HH 16
#define HDD 64
#define MM (BB * NN)           // 16384 rows
#define KVC 16                 // kv partial chunks (256 rows each)

// ---------------- scratch (device globals; no allocation allowed) ----------
__device__ __half g_hq[(size_t)MM * DIMM];
__device__ __half g_hk[(size_t)MM * DIMM];
__device__ __half g_hv[(size_t)MM * DIMM];
__device__ __half g_Q16[(size_t)MM * DIMM];
__device__ __half g_K16[(size_t)MM * DIMM];
__device__ __half g_V16[(size_t)MM * DIMM];
__device__ __half g_hA[(size_t)MM * DIMM];
__device__ __half g_Wh[4 * DIMM * DIMM];
__device__ float  g_kvp[(size_t)KVC * BB * HH * HDD * HDD];
__device__ float  g_ksp[(size_t)KVC * BB * HH * HDD];
__device__ __half g_kv16[BB * HH * HDD * HDD];
__device__ float  g_ksum[BB * HH * HDD];

__device__ __forceinline__ void cp_async16(void* smem_ptr, const void* gmem_ptr) {
    unsigned int s = (unsigned int)__cvta_generic_to_shared(smem_ptr);
    asm volatile("cp.async.cg.shared.global [%0], [%1], 16;\n" :: "r"(s), "l"(gmem_ptr));
}

// ---------------- fused fp32 -> fp16 conversion (RN) ----------------
__global__ void cvt_all(const float* __restrict__ A0, const float* __restrict__ A1,
                        const float* __restrict__ A2,
                        const float* __restrict__ W0, const float* __restrict__ W1,
                        const float* __restrict__ W2, const float* __restrict__ W3,
                        __half* __restrict__ D0, __half* __restrict__ D1,
                        __half* __restrict__ D2, __half* __restrict__ Wh) {
    const int y = blockIdx.y;
    int i = blockIdx.x * blockDim.x + threadIdx.x;
    if (y < 3) {
        const float* srcs[3] = {A0, A1, A2};
        __half* dsts[3] = {D0, D1, D2};
        if (i < (MM * DIMM) / 4) {
            float4 v = ((const float4*)srcs[y])[i];
            __half2* d = (__half2*)dsts[y];
            d[2 * i + 0] = __floats2half2_rn(v.x, v.y);
            d[2 * i + 1] = __floats2half2_rn(v.z, v.w);
        }
    } else {
        if (i < (4 * DIMM * DIMM) / 4) {
            const float* ws[4] = {W0, W1, W2, W3};
            const int m = i >> 18;
            const int j = i & 262143;
            float4 v = ((const float4*)ws[m])[j];
            __half2* d = (__half2*)(Wh + (size_t)m * DIMM * DIMM);
            d[2 * j + 0] = __floats2half2_rn(v.x, v.y);
            d[2 * j + 1] = __floats2half2_rn(v.z, v.w);
        }
    }
}

// ==== fp16 GEMM (R12 shape): 128x128 block, 8 warps, 32x64 tile, KC=64 ====
#define KC 64
#define HPAD 72
#define HTILE (128 * HPAD)
#define HSTAGE (2 * HTILE)
#define GEMM_DSMEM (2 * HSTAGE * 2)        // 73728 bytes

extern __shared__ __align__(16) __half dsm_h[];

struct GemmCore {
    wmma::fragment<wmma::accumulator, 16, 16, 16, float> acc[2][4];
    int t, w, wm, wn;

    __device__ __forceinline__ void init(int tid) {
        t = tid; w = t >> 5; wm = w >> 1; wn = w & 1;
#pragma unroll
        for (int i = 0; i < 2; i++)
#pragma unroll
            for (int j = 0; j < 4; j++)
                wmma::fill_fragment(acc[i][j], 0.0f);
    }

    __device__ __forceinline__ void load_chunk(const __half* Abase, const __half* Bbase,
                                               int kc, int s) {
        __half* As = dsm_h + s * HSTAGE;
        __half* Bs = As + HTILE;
        const int k0 = kc * KC;
#pragma unroll
        for (int j = 0; j < 4; j++) {
            int u = t + j * 256;
            int row = u >> 3;
            int c8 = (u & 7) * 8;
            cp_async16(&As[row * HPAD + c8], Abase + (size_t)row * DIMM + k0 + c8);
            cp_async16(&Bs[row * HPAD + c8], Bbase + (size_t)row * DIMM + k0 + c8);
        }
    }

    __device__ __forceinline__ void mainloop(const __half* Abase, const __half* Bbase) {
        load_chunk(Abase, Bbase, 0, 0);
        asm volatile("cp.async.commit_group;\n");
        const int NCH = DIMM / KC;   // 16
        for (int i = 0; i < NCH; i++) {
            const int s = i & 1;
            if (i + 1 < NCH) {
                load_chunk(Abase, Bbase, i + 1, s ^ 1);
                asm volatile("cp.async.commit_group;\n");
                asm volatile("cp.async.wait_group 1;\n");
            } else {
                asm volatile("cp.async.wait_group 0;\n");
            }
            __syncthreads();

            const __half* As = dsm_h + s * HSTAGE;
            const __half* Bs = As + HTILE;
#pragma unroll
            for (int kk = 0; kk < KC; kk += 16) {
                wmma::fragment<wmma::matrix_a, 16, 16, 16, __half, wmma::row_major> af[2];
                wmma::fragment<wmma::matrix_b, 16, 16, 16, __half, wmma::col_major> bf[4];
#pragma unroll
                for (int x = 0; x < 2; x++)
                    wmma::load_matrix_sync(af[x], As + (wm * 32 + x * 16) * HPAD + kk, HPAD);
#pragma unroll
                for (int y = 0; y < 4; y++)
                    wmma::load_matrix_sync(bf[y], Bs + (wn * 64 + y * 16) * HPAD + kk, HPAD);
#pragma unroll
                for (int x = 0; x < 2; x++)
#pragma unroll
                    for (int y = 0; y < 4; y++)
                        wmma::mma_sync(acc[x][y], af[x], bf[y], acc[x][y]);
            }
            __syncthreads();
        }
    }

    // single-pass epilogue: full 128x132 fp32 tile in smem
    __device__ __forceinline__ void epilogue(const float* bias,
                                             float* Cf, __half* Ch, int do_relu,
                                             int m0, int n0) {
        float* Ct = (float*)dsm_h;
#pragma unroll
        for (int x = 0; x < 2; x++)
#pragma unroll
            for (int y = 0; y < 4; y++)
                wmma::store_matrix_sync(Ct + (wm * 32 + x * 16) * 132 + wn * 64 + y * 16,
                                        acc[x][y], 132, wmma::mem_row_major);
        __syncthreads();
#pragma unroll
        for (int i = 0; i < 16; i++) {
            int u = t + i * 256;
            int r = u >> 5;
            int c = (u & 31) * 4;
            int row = m0 + r;
            float4 v = *(float4*)(Ct + r * 132 + c);
            v.x += bias[n0 + c + 0];
            v.y += bias[n0 + c + 1];
            v.z += bias[n0 + c + 2];
            v.w += bias[n0 + c + 3];
            if (do_relu) {
                v.x = fmaxf(v.x, 0.0f); v.y = fmaxf(v.y, 0.0f);
                v.z = fmaxf(v.z, 0.0f); v.w = fmaxf(v.w, 0.0f);
            }
            if (Ch != nullptr) {
                __half2* p = (__half2*)(Ch + (size_t)row * DIMM + n0 + c);
                p[0] = __floats2half2_rn(v.x, v.y);
                p[1] = __floats2half2_rn(v.z, v.w);
            } else {
                *(float4*)(Cf + (size_t)row * DIMM + n0 + c) = v;
            }
        }
    }
};

__global__ void __launch_bounds__(256, 2)
gemm_qkv(const __half* __restrict__ hq, const __half* __restrict__ hk,
         const __half* __restrict__ hv, const __half* __restrict__ Wh,
         const float* __restrict__ bq, const float* __restrict__ bk,
         const float* __restrict__ bv,
         __half* __restrict__ Q16, __half* __restrict__ K16, __half* __restrict__ V16) {
    const int z = blockIdx.z;
    const __half* A = (z == 0) ? hq : (z == 1) ? hk : hv;
    const __half* W = Wh + (size_t)z * DIMM * DIMM;
    const float* bias = (z == 0) ? bq : (z == 1) ? bk : bv;
    __half* out = (z == 0) ? Q16 : (z == 1) ? K16 : V16;
    const int do_relu = (z < 2);

    GemmCore g;
    g.init(threadIdx.x);
    const int n0 = blockIdx.x * 128;
    const int m0 = blockIdx.y * 128;
    g.mainloop(A + (size_t)m0 * DIMM, W + (size_t)n0 * DIMM);
    g.epilogue(bias, nullptr, out, do_relu, m0, n0);
}

__global__ void __launch_bounds__(256, 2)
gemm_one(const __half* __restrict__ A, const __half* __restrict__ W,
         const float* __restrict__ bias, float* __restrict__ Cf) {
    GemmCore g;
    g.init(threadIdx.x);
    const int n0 = blockIdx.x * 128;
    const int m0 = blockIdx.y * 128;
    g.mainloop(A + (size_t)m0 * DIMM, W + (size_t)n0 * DIMM);
    g.epilogue(bias, Cf, nullptr, 0, m0, n0);
}

// ---- kv partials via fp16 WMMA; key-padding mask applied here ------------
#define KVPAD 72
__global__ void __launch_bounds__(128)
kv_h(const __half* __restrict__ K, const __half* __restrict__ V,
     const int* __restrict__ mask,
     float* __restrict__ kvp, float* __restrict__ ksp) {
    __shared__ __align__(16) __half Ks[128][KVPAD];
    __shared__ __align__(16) __half Vs[128][KVPAD];
    __shared__ float ksb[128];

    const int bh = blockIdx.y;
    const int b = bh >> 4, h = bh & 15;
    const int chunk = blockIdx.x;
    const int t = threadIdx.x;
    const int w = t >> 5;
    const int d0 = w * 16;
    const int dcol = t & 63, rhalf = t >> 6;

    wmma::fragment<wmma::accumulator, 16, 16, 16, float> acc[4];
#pragma unroll
    for (int e = 0; e < 4; e++) wmma::fill_fragment(acc[e], 0.0f);
    float ksacc = 0.0f;

#pragma unroll
    for (int sub = 0; sub < 2; sub++) {
        const int n0 = chunk * 256 + sub * 128;
#pragma unroll
        for (int j = 0; j < 8; j++) {
            int u = t + j * 128;
            int row = u >> 3;
            int c8 = (u & 7) * 8;
            const size_t goff = (size_t)(b * NN + n0 + row) * DIMM + h * HDD + c8;
            cp_async16(&Ks[row][c8], K + goff);
            cp_async16(&Vs[row][c8], V + goff);
        }
        asm volatile("cp.async.commit_group;\n");
        asm volatile("cp.async.wait_group 0;\n");
        __syncthreads();

        if (mask[b * NN + n0 + t] != 0) {
            uint4 z = {0, 0, 0, 0};
#pragma unroll
            for (int c16 = 0; c16 < 8; c16++)
                *(uint4*)&Ks[t][c16 * 8] = z;
        }
        __syncthreads();

#pragma unroll 16
        for (int r = rhalf * 64; r < rhalf * 64 + 64; r++)
            ksacc += __half2float(Ks[r][dcol]);

#pragma unroll
        for (int ns = 0; ns < 128; ns += 16) {
            wmma::fragment<wmma::matrix_a, 16, 16, 16, __half, wmma::col_major> a;
            wmma::load_matrix_sync(a, &Ks[ns][d0], KVPAD);
#pragma unroll
            for (int e = 0; e < 4; e++) {
                wmma::fragment<wmma::matrix_b, 16, 16, 16, __half, wmma::row_major> bfr;
                wmma::load_matrix_sync(bfr, &Vs[ns][e * 16], KVPAD);
                wmma::mma_sync(acc[e], a, bfr, acc[e]);
            }
        }
        __syncthreads();
    }

    float* dst = kvp + ((size_t)chunk * 64 + bh) * (HDD * HDD);
#pragma unroll
    for (int e = 0; e < 4; e++)
        wmma::store_matrix_sync(dst + d0 * 64 + e * 16, acc[e], 64, wmma::mem_row_major);

    ksb[t] = ksacc;
    __syncthreads();
    if (t < 64) ksp[((size_t)chunk * 64 + bh) * HDD + t] = ksb[t] + ksb[t + 64];
}

// ---- parallel reduce: grid (bh, quarter); each CTA reduces 1024 kv els ----
__global__ void __launch_bounds__(256)
reduce_kv(const float* __restrict__ kvp, const float* __restrict__ ksp,
          __half* __restrict__ kv16, float* __restrict__ ksum) {
    const int bh = blockIdx.x;
    const int q = blockIdx.y;            // 0..3
    const int t = threadIdx.x;
    const int base = q * 1024;

    // each thread: 4 elements (float4) of the 1024-slab
    const int i4 = base + t * 4;
    float4 s = {0.0f, 0.0f, 0.0f, 0.0f};
#pragma unroll
    for (int c = 0; c < KVC; c++) {
        const float4 v = *(const float4*)(kvp + ((size_t)c * 64 + bh) * (HDD * HDD) + i4);
        s.x += v.x; s.y += v.y; s.z += v.z; s.w += v.w;
    }
    __half2* d = (__half2*)(kv16 + (size_t)bh * (HDD * HDD) + i4);
    d[0] = __floats2half2_rn(s.x, s.y);
    d[1] = __floats2half2_rn(s.z, s.w);

    if (q == 0 && t < 64) {
        float ss = 0.0f;
#pragma unroll
        for (int c = 0; c < KVC; c++)
            ss += ksp[((size_t)c * 64 + bh) * HDD + t];
        ksum[bh * HDD + t] = ss;
    }
}

// ---- WMMA attn: out = (Q @ kv) / (Q.ksum + eps), fp16 in/out --------------
#define APAD 72
#define ATTN_OFF_KV 18432
#define ATTN_OFF_KSS 34816
#define ATTN_OFF_DEN 35072
#define ATTN_DSMEM 35584

__global__ void __launch_bounds__(128)
attn_h(const __half* __restrict__ Q, const __half* __restrict__ kv16,
       const float* __restrict__ ksum, __half* __restrict__ out) {
    char* dyn = (char*)dsm_h;
    __half* Qs = (__half*)dyn;
    __half* KVs = (__half*)(dyn + ATTN_OFF_KV);
    float* Cs = (float*)dyn;
    float* kss = (float*)(dyn + ATTN_OFF_KSS);
    float* dn = (float*)(dyn + ATTN_OFF_DEN);

    const int bh = blockIdx.y;
    const int b = bh >> 4, h = bh & 15;
    const int nbase = blockIdx.x * 128;
    const int t = threadIdx.x;
    const int w = t >> 5;

#pragma unroll
    for (int j = 0; j < 8; j++) {
        int u = t + j * 128;
        int row = u >> 3;
        int c8 = (u & 7) * 8;
        cp_async16(&Qs[row * APAD + c8],
                   Q + (size_t)(b * NN + nbase + row) * DIMM + h * HDD + c8);
    }
#pragma unroll
    for (int j = 0; j < 4; j++) {
        int u = t + j * 128;
        int row = u >> 3;
        int c8 = (u & 7) * 8;
        cp_async16(&KVs[row * APAD + c8], kv16 + (size_t)bh * 4096 + row * 64 + c8);
    }
    if (t < 64) kss[t] = ksum[bh * 64 + t];
    asm volatile("cp.async.commit_group;\n");
    asm volatile("cp.async.wait_group 0;\n");
    __syncthreads();

    {
        float p = 0.0f;
#pragma unroll 16
        for (int d = 0; d < 64; d++)
            p += __half2float(Qs[t * APAD + d]) * kss[d];
        dn[t] = 1.0f / (p + 1e-6f);
    }

    wmma::fragment<wmma::accumulator, 16, 16, 16, float> acc[2][4];
#pragma unroll
    for (int x = 0; x < 2; x++)
#pragma unroll
        for (int y = 0; y < 4; y++)
            wmma::fill_fragment(acc[x][y], 0.0f);
#pragma unroll
    for (int k = 0; k < 64; k += 16) {
        wmma::fragment<wmma::matrix_a, 16, 16, 16, __half, wmma::row_major> af[2];
        wmma::fragment<wmma::matrix_b, 16, 16, 16, __half, wmma::row_major> bf[4];
#pragma unroll
        for (int x = 0; x < 2; x++)
            wmma::load_matrix_sync(af[x], Qs + (w * 32 + x * 16) * APAD + k, APAD);
#pragma unroll
        for (int y = 0; y < 4; y++)
            wmma::load_matrix_sync(bf[y], KVs + k * APAD + y * 16, APAD);
#pragma unroll
        for (int x = 0; x < 2; x++)
#pragma unroll
            for (int y = 0; y < 4; y++)
                wmma::mma_sync(acc[x][y], af[x], bf[y], acc[x][y]);
    }
    __syncthreads();

#pragma unroll
    for (int x = 0; x < 2; x++)
#pragma unroll
        for (int y = 0; y < 4; y++)
            wmma::store_matrix_sync(Cs + (w * 32 + x * 16) * 68 + y * 16,
                                    acc[x][y], 68, wmma::mem_row_major);
    __syncthreads();

#pragma unroll
    for (int i = 0; i < 32; i++) {
        int u = t + i * 128;
        int row = u >> 5;
        int e2 = (u & 31) * 2;
        float sc = dn[row];
        __half2 hv2 = __floats2half2_rn(Cs[row * 68 + e2] * sc, Cs[row * 68 + e2 + 1] * sc);
        *(__half2*)(out + (size_t)(b * NN + nbase + row) * DIMM + h * HDD + e2) = hv2;
    }
}

// ---------------- launch ----------------
extern "C" void kernel_launch(void* const* d_in, const int* in_sizes, int n_in,
                              void* d_out, int out_size) {
    const float* query = (const float*)d_in[0];
    const float* key   = (const float*)d_in[1];
    const float* value = (const float*)d_in[2];
    const float* Wq = (const float*)d_in[3];
    const float* bq = (const float*)d_in[4];
    const float* Wk = (const float*)d_in[5];
    const float* bk = (const float*)d_in[6];
    const float* Wv = (const float*)d_in[7];
    const float* bv = (const float*)d_in[8];
    const float* Wo = (const float*)d_in[9];
    const float* bo = (const float*)d_in[10];
    const int* mask = (const int*)d_in[11];

    float *KVPp, *KSPp, *KSp;
    __half *hq, *hk, *hv, *Q16, *K16, *V16, *hA, *Wh, *KV16;
    cudaGetSymbolAddress((void**)&hq, g_hq);
    cudaGetSymbolAddress((void**)&hk, g_hk);
    cudaGetSymbolAddress((void**)&hv, g_hv);
    cudaGetSymbolAddress((void**)&Q16, g_Q16);
    cudaGetSymbolAddress((void**)&K16, g_K16);
    cudaGetSymbolAddress((void**)&V16, g_V16);
    cudaGetSymbolAddress((void**)&hA, g_hA);
    cudaGetSymbolAddress((void**)&Wh, g_Wh);
    cudaGetSymbolAddress((void**)&KVPp, g_kvp);
    cudaGetSymbolAddress((void**)&KSPp, g_ksp);
    cudaGetSymbolAddress((void**)&KV16, g_kv16);
    cudaGetSymbolAddress((void**)&KSp, g_ksum);

    cudaFuncSetAttribute(gemm_qkv, cudaFuncAttributeMaxDynamicSharedMemorySize, GEMM_DSMEM);
    cudaFuncSetAttribute(gemm_one, cudaFuncAttributeMaxDynamicSharedMemorySize, GEMM_DSMEM);

    dim3 ggrid3(DIMM / 128, MM / 128, 3);
    dim3 ggrid(DIMM / 128, MM / 128);

    cvt_all<<<dim3(16384, 4), 256>>>(query, key, value, Wq, Wk, Wv, Wo,
                                     hq, hk, hv, Wh);
    gemm_qkv<<<ggrid3, 256, GEMM_DSMEM>>>(hq, hk, hv, Wh, bq, bk, bv, Q16, K16, V16);
    kv_h<<<dim3(KVC, 64), 128>>>(K16, V16, mask, KVPp, KSPp);
    reduce_kv<<<dim3(64, 4), 256>>>(KVPp, KSPp, KV16, KSp);
    attn_h<<<dim3(NN / 128, 64), 128, ATTN_DSMEM>>>(Q16, KV16, KSp, hA);
    gemm_one<<<ggrid, 256, GEMM_DSMEM>>>(hA, Wh + 3 * (size_t)DIMM * DIMM, bo, (float*)d_out);
}

// round 17
// speedup vs baseline: 1.1022x; 1.0897x over previous
#include <cuda_runtime.h>
#include <cuda_fp16.h>
#include <mma.h>
#include <cstdint>

using namespace nvcuda;

// Problem constants
#define BB 4
#define NN 4096
#define DIMM 1024
#define HH 16
#define HDD 64
#define MM (BB * NN)           // 16384 rows
#define KVC 16                 // kv partial chunks (256 rows each)

// ---------------- scratch (device globals; no allocation allowed) ----------
__device__ __half g_hq[(size_t)MM * DIMM];
__device__ __half g_hk[(size_t)MM * DIMM];
__device__ __half g_hv[(size_t)MM * DIMM];
__device__ __half g_Q16[(size_t)MM * DIMM];
__device__ __half g_K16[(size_t)MM * DIMM];
__device__ __half g_V16[(size_t)MM * DIMM];
__device__ __half g_hA[(size_t)MM * DIMM];
__device__ __half g_Wh[4 * DIMM * DIMM];
__device__ float  g_kvp[(size_t)KVC * BB * HH * HDD * HDD];
__device__ float  g_ksp[(size_t)KVC * BB * HH * HDD];
__device__ __half g_kv16[BB * HH * HDD * HDD];
__device__ float  g_ksum[BB * HH * HDD];

__device__ __forceinline__ void cp_async16(void* smem_ptr, const void* gmem_ptr) {
    unsigned int s = (unsigned int)__cvta_generic_to_shared(smem_ptr);
    asm volatile("cp.async.cg.shared.global [%0], [%1], 16;\n" :: "r"(s), "l"(gmem_ptr));
}

// ---------------- fused fp32 -> fp16 conversion (RN), MLP=4 ---------------
// grid (4096, 4): y 0..2 = activations (4 strided float4 each), y 3 = weights.
#define ACT_F4 ((MM * DIMM) / 4)        // 4194304 float4
#define ACT_STRIDE (ACT_F4 / 4)         // 1048576
#define W_F4 ((4 * DIMM * DIMM) / 4)    // 1048576 float4

__global__ void cvt_all(const float* __restrict__ A0, const float* __restrict__ A1,
                        const float* __restrict__ A2,
                        const float* __restrict__ W0, const float* __restrict__ W1,
                        const float* __restrict__ W2, const float* __restrict__ W3,
                        __half* __restrict__ D0, __half* __restrict__ D1,
                        __half* __restrict__ D2, __half* __restrict__ Wh) {
    const int y = blockIdx.y;
    const int i = blockIdx.x * blockDim.x + threadIdx.x;   // 0..1048575
    if (y < 3) {
        const float* srcs[3] = {A0, A1, A2};
        __half* dsts[3] = {D0, D1, D2};
        const float4* s = (const float4*)srcs[y];
        __half2* d = (__half2*)dsts[y];
        // MLP=4: four independent strided float4 loads in flight
        float4 v0 = s[i];
        float4 v1 = s[i + ACT_STRIDE];
        float4 v2 = s[i + 2 * ACT_STRIDE];
        float4 v3 = s[i + 3 * ACT_STRIDE];
        d[2 * i + 0] = __floats2half2_rn(v0.x, v0.y);
        d[2 * i + 1] = __floats2half2_rn(v0.z, v0.w);
        d[2 * (i + ACT_STRIDE) + 0] = __floats2half2_rn(v1.x, v1.y);
        d[2 * (i + ACT_STRIDE) + 1] = __floats2half2_rn(v1.z, v1.w);
        d[2 * (i + 2 * ACT_STRIDE) + 0] = __floats2half2_rn(v2.x, v2.y);
        d[2 * (i + 2 * ACT_STRIDE) + 1] = __floats2half2_rn(v2.z, v2.w);
        d[2 * (i + 3 * ACT_STRIDE) + 0] = __floats2half2_rn(v3.x, v3.y);
        d[2 * (i + 3 * ACT_STRIDE) + 1] = __floats2half2_rn(v3.z, v3.w);
    } else {
        // weights: 1M float4 over 1M threads, one each
        if (i < W_F4) {
            const float* ws[4] = {W0, W1, W2, W3};
            const int m = i >> 18;
            const int j = i & 262143;
            float4 v = ((const float4*)ws[m])[j];
            __half2* d = (__half2*)(Wh + (size_t)m * DIMM * DIMM);
            d[2 * j + 0] = __floats2half2_rn(v.x, v.y);
            d[2 * j + 1] = __floats2half2_rn(v.z, v.w);
        }
    }
}

// ==== fp16 GEMM (R12 shape): 128x128 block, 8 warps, 32x64 tile, KC=64 ====
#define KC 64
#define HPAD 72
#define HTILE (128 * HPAD)
#define HSTAGE (2 * HTILE)
#define GEMM_DSMEM (2 * HSTAGE * 2)        // 73728 bytes

extern __shared__ __align__(16) __half dsm_h[];

struct GemmCore {
    wmma::fragment<wmma::accumulator, 16, 16, 16, float> acc[2][4];
    int t, w, wm, wn;

    __device__ __forceinline__ void init(int tid) {
        t = tid; w = t >> 5; wm = w >> 1; wn = w & 1;
#pragma unroll
        for (int i = 0; i < 2; i++)
#pragma unroll
            for (int j = 0; j < 4; j++)
                wmma::fill_fragment(acc[i][j], 0.0f);
    }

    __device__ __forceinline__ void load_chunk(const __half* Abase, const __half* Bbase,
                                               int kc, int s) {
        __half* As = dsm_h + s * HSTAGE;
        __half* Bs = As + HTILE;
        const int k0 = kc * KC;
#pragma unroll
        for (int j = 0; j < 4; j++) {
            int u = t + j * 256;
            int row = u >> 3;
            int c8 = (u & 7) * 8;
            cp_async16(&As[row * HPAD + c8], Abase + (size_t)row * DIMM + k0 + c8);
            cp_async16(&Bs[row * HPAD + c8], Bbase + (size_t)row * DIMM + k0 + c8);
        }
    }

    __device__ __forceinline__ void mainloop(const __half* Abase, const __half* Bbase) {
        load_chunk(Abase, Bbase, 0, 0);
        asm volatile("cp.async.commit_group;\n");
        const int NCH = DIMM / KC;   // 16
        for (int i = 0; i < NCH; i++) {
            const int s = i & 1;
            if (i + 1 < NCH) {
                load_chunk(Abase, Bbase, i + 1, s ^ 1);
                asm volatile("cp.async.commit_group;\n");
                asm volatile("cp.async.wait_group 1;\n");
            } else {
                asm volatile("cp.async.wait_group 0;\n");
            }
            __syncthreads();

            const __half* As = dsm_h + s * HSTAGE;
            const __half* Bs = As + HTILE;
#pragma unroll
            for (int kk = 0; kk < KC; kk += 16) {
                wmma::fragment<wmma::matrix_a, 16, 16, 16, __half, wmma::row_major> af[2];
                wmma::fragment<wmma::matrix_b, 16, 16, 16, __half, wmma::col_major> bf[4];
#pragma unroll
                for (int x = 0; x < 2; x++)
                    wmma::load_matrix_sync(af[x], As + (wm * 32 + x * 16) * HPAD + kk, HPAD);
#pragma unroll
                for (int y = 0; y < 4; y++)
                    wmma::load_matrix_sync(bf[y], Bs + (wn * 64 + y * 16) * HPAD + kk, HPAD);
#pragma unroll
                for (int x = 0; x < 2; x++)
#pragma unroll
                    for (int y = 0; y < 4; y++)
                        wmma::mma_sync(acc[x][y], af[x], bf[y], acc[x][y]);
            }
            __syncthreads();
        }
    }

    // single-pass epilogue: full 128x132 fp32 tile in smem
    __device__ __forceinline__ void epilogue(const float* bias,
                                             float* Cf, __half* Ch, int do_relu,
                                             int m0, int n0) {
        float* Ct = (float*)dsm_h;
#pragma unroll
        for (int x = 0; x < 2; x++)
#pragma unroll
            for (int y = 0; y < 4; y++)
                wmma::store_matrix_sync(Ct + (wm * 32 + x * 16) * 132 + wn * 64 + y * 16,
                                        acc[x][y], 132, wmma::mem_row_major);
        __syncthreads();
#pragma unroll
        for (int i = 0; i < 16; i++) {
            int u = t + i * 256;
            int r = u >> 5;
            int c = (u & 31) * 4;
            int row = m0 + r;
            float4 v = *(float4*)(Ct + r * 132 + c);
            v.x += bias[n0 + c + 0];
            v.y += bias[n0 + c + 1];
            v.z += bias[n0 + c + 2];
            v.w += bias[n0 + c + 3];
            if (do_relu) {
                v.x = fmaxf(v.x, 0.0f); v.y = fmaxf(v.y, 0.0f);
                v.z = fmaxf(v.z, 0.0f); v.w = fmaxf(v.w, 0.0f);
            }
            if (Ch != nullptr) {
                __half2* p = (__half2*)(Ch + (size_t)row * DIMM + n0 + c);
                p[0] = __floats2half2_rn(v.x, v.y);
                p[1] = __floats2half2_rn(v.z, v.w);
            } else {
                *(float4*)(Cf + (size_t)row * DIMM + n0 + c) = v;
            }
        }
    }
};

__global__ void __launch_bounds__(256, 2)
gemm_qkv(const __half* __restrict__ hq, const __half* __restrict__ hk,
         const __half* __restrict__ hv, const __half* __restrict__ Wh,
         const float* __restrict__ bq, const float* __restrict__ bk,
         const float* __restrict__ bv,
         __half* __restrict__ Q16, __half* __restrict__ K16, __half* __restrict__ V16) {
    const int z = blockIdx.z;
    const __half* A = (z == 0) ? hq : (z == 1) ? hk : hv;
    const __half* W = Wh + (size_t)z * DIMM * DIMM;
    const float* bias = (z == 0) ? bq : (z == 1) ? bk : bv;
    __half* out = (z == 0) ? Q16 : (z == 1) ? K16 : V16;
    const int do_relu = (z < 2);

    GemmCore g;
    g.init(threadIdx.x);
    const int n0 = blockIdx.x * 128;
    const int m0 = blockIdx.y * 128;
    g.mainloop(A + (size_t)m0 * DIMM, W + (size_t)n0 * DIMM);
    g.epilogue(bias, nullptr, out, do_relu, m0, n0);
}

__global__ void __launch_bounds__(256, 2)
gemm_one(const __half* __restrict__ A, const __half* __restrict__ W,
         const float* __restrict__ bias, float* __restrict__ Cf) {
    GemmCore g;
    g.init(threadIdx.x);
    const int n0 = blockIdx.x * 128;
    const int m0 = blockIdx.y * 128;
    g.mainloop(A + (size_t)m0 * DIMM, W + (size_t)n0 * DIMM);
    g.epilogue(bias, Cf, nullptr, 0, m0, n0);
}

// ---- kv partials via fp16 WMMA; key-padding mask applied here ------------
#define KVPAD 72
__global__ void __launch_bounds__(128)
kv_h(const __half* __restrict__ K, const __half* __restrict__ V,
     const int* __restrict__ mask,
     float* __restrict__ kvp, float* __restrict__ ksp) {
    __shared__ __align__(16) __half Ks[128][KVPAD];
    __shared__ __align__(16) __half Vs[128][KVPAD];
    __shared__ float ksb[128];

    const int bh = blockIdx.y;
    const int b = bh >> 4, h = bh & 15;
    const int chunk = blockIdx.x;
    const int t = threadIdx.x;
    const int w = t >> 5;
    const int d0 = w * 16;
    const int dcol = t & 63, rhalf = t >> 6;

    wmma::fragment<wmma::accumulator, 16, 16, 16, float> acc[4];
#pragma unroll
    for (int e = 0; e < 4; e++) wmma::fill_fragment(acc[e], 0.0f);
    float ksacc = 0.0f;

#pragma unroll
    for (int sub = 0; sub < 2; sub++) {
        const int n0 = chunk * 256 + sub * 128;
#pragma unroll
        for (int j = 0; j < 8; j++) {
            int u = t + j * 128;
            int row = u >> 3;
            int c8 = (u & 7) * 8;
            const size_t goff = (size_t)(b * NN + n0 + row) * DIMM + h * HDD + c8;
            cp_async16(&Ks[row][c8], K + goff);
            cp_async16(&Vs[row][c8], V + goff);
        }
        asm volatile("cp.async.commit_group;\n");
        asm volatile("cp.async.wait_group 0;\n");
        __syncthreads();

        if (mask[b * NN + n0 + t] != 0) {
            uint4 z = {0, 0, 0, 0};
#pragma unroll
            for (int c16 = 0; c16 < 8; c16++)
                *(uint4*)&Ks[t][c16 * 8] = z;
        }
        __syncthreads();

#pragma unroll 16
        for (int r = rhalf * 64; r < rhalf * 64 + 64; r++)
            ksacc += __half2float(Ks[r][dcol]);

#pragma unroll
        for (int ns = 0; ns < 128; ns += 16) {
            wmma::fragment<wmma::matrix_a, 16, 16, 16, __half, wmma::col_major> a;
            wmma::load_matrix_sync(a, &Ks[ns][d0], KVPAD);
#pragma unroll
            for (int e = 0; e < 4; e++) {
                wmma::fragment<wmma::matrix_b, 16, 16, 16, __half, wmma::row_major> bfr;
                wmma::load_matrix_sync(bfr, &Vs[ns][e * 16], KVPAD);
                wmma::mma_sync(acc[e], a, bfr, acc[e]);
            }
        }
        __syncthreads();
    }

    float* dst = kvp + ((size_t)chunk * 64 + bh) * (HDD * HDD);
#pragma unroll
    for (int e = 0; e < 4; e++)
        wmma::store_matrix_sync(dst + d0 * 64 + e * 16, acc[e], 64, wmma::mem_row_major);

    ksb[t] = ksacc;
    __syncthreads();
    if (t < 64) ksp[((size_t)chunk * 64 + bh) * HDD + t] = ksb[t] + ksb[t + 64];
}

// ---- parallel reduce: grid (bh, eighth); 128 thr x 4 els = 512-el slab ----
__global__ void __launch_bounds__(128)
reduce_kv(const float* __restrict__ kvp, const float* __restrict__ ksp,
          __half* __restrict__ kv16, float* __restrict__ ksum) {
    const int bh = blockIdx.x;
    const int q = blockIdx.y;            // 0..7
    const int t = threadIdx.x;
    const int i4 = q * 512 + t * 4;

    float4 s = {0.0f, 0.0f, 0.0f, 0.0f};
#pragma unroll
    for (int c = 0; c < KVC; c++) {
        const float4 v = *(const float4*)(kvp + ((size_t)c * 64 + bh) * (HDD * HDD) + i4);
        s.x += v.x; s.y += v.y; s.z += v.z; s.w += v.w;
    }
    __half2* d = (__half2*)(kv16 + (size_t)bh * (HDD * HDD) + i4);
    d[0] = __floats2half2_rn(s.x, s.y);
    d[1] = __floats2half2_rn(s.z, s.w);

    if (q == 0 && t < 64) {
        float ss = 0.0f;
#pragma unroll
        for (int c = 0; c < KVC; c++)
            ss += ksp[((size_t)c * 64 + bh) * HDD + t];
        ksum[bh * HDD + t] = ss;
    }
}

// ---- WMMA attn: out = (Q @ kv) / (Q.ksum + eps), fp16 in/out --------------
#define APAD 72
#define ATTN_OFF_KV 18432
#define ATTN_OFF_KSS 34816
#define ATTN_OFF_DEN 35072
#define ATTN_DSMEM 35584

__global__ void __launch_bounds__(128)
attn_h(const __half* __restrict__ Q, const __half* __restrict__ kv16,
       const float* __restrict__ ksum, __half* __restrict__ out) {
    char* dyn = (char*)dsm_h;
    __half* Qs = (__half*)dyn;
    __half* KVs = (__half*)(dyn + ATTN_OFF_KV);
    float* Cs = (float*)dyn;
    float* kss = (float*)(dyn + ATTN_OFF_KSS);
    float* dn = (float*)(dyn + ATTN_OFF_DEN);

    const int bh = blockIdx.y;
    const int b = bh >> 4, h = bh & 15;
    const int nbase = blockIdx.x * 128;
    const int t = threadIdx.x;
    const int w = t >> 5;

#pragma unroll
    for (int j = 0; j < 8; j++) {
        int u = t + j * 128;
        int row = u >> 3;
        int c8 = (u & 7) * 8;
        cp_async16(&Qs[row * APAD + c8],
                   Q + (size_t)(b * NN + nbase + row) * DIMM + h * HDD + c8);
    }
#pragma unroll
    for (int j = 0; j < 4; j++) {
        int u = t + j * 128;
        int row = u >> 3;
        int c8 = (u & 7) * 8;
        cp_async16(&KVs[row * APAD + c8], kv16 + (size_t)bh * 4096 + row * 64 + c8);
    }
    if (t < 64) kss[t] = ksum[bh * 64 + t];
    asm volatile("cp.async.commit_group;\n");
    asm volatile("cp.async.wait_group 0;\n");
    __syncthreads();

    {
        float p = 0.0f;
#pragma unroll 16
        for (int d = 0; d < 64; d++)
            p += __half2float(Qs[t * APAD + d]) * kss[d];
        dn[t] = 1.0f / (p + 1e-6f);
    }

    wmma::fragment<wmma::accumulator, 16, 16, 16, float> acc[2][4];
#pragma unroll
    for (int x = 0; x < 2; x++)
#pragma unroll
        for (int y = 0; y < 4; y++)
            wmma::fill_fragment(acc[x][y], 0.0f);
#pragma unroll
    for (int k = 0; k < 64; k += 16) {
        wmma::fragment<wmma::matrix_a, 16, 16, 16, __half, wmma::row_major> af[2];
        wmma::fragment<wmma::matrix_b, 16, 16, 16, __half, wmma::row_major> bf[4];
#pragma unroll
        for (int x = 0; x < 2; x++)
            wmma::load_matrix_sync(af[x], Qs + (w * 32 + x * 16) * APAD + k, APAD);
#pragma unroll
        for (int y = 0; y < 4; y++)
            wmma::load_matrix_sync(bf[y], KVs + k * APAD + y * 16, APAD);
#pragma unroll
        for (int x = 0; x < 2; x++)
#pragma unroll
            for (int y = 0; y < 4; y++)
                wmma::mma_sync(acc[x][y], af[x], bf[y], acc[x][y]);
    }
    __syncthreads();

#pragma unroll
    for (int x = 0; x < 2; x++)
#pragma unroll
        for (int y = 0; y < 4; y++)
            wmma::store_matrix_sync(Cs + (w * 32 + x * 16) * 68 + y * 16,
                                    acc[x][y], 68, wmma::mem_row_major);
    __syncthreads();

#pragma unroll
    for (int i = 0; i < 32; i++) {
        int u = t + i * 128;
        int row = u >> 5;
        int e2 = (u & 31) * 2;
        float sc = dn[row];
        __half2 hv2 = __floats2half2_rn(Cs[row * 68 + e2] * sc, Cs[row * 68 + e2 + 1] * sc);
        *(__half2*)(out + (size_t)(b * NN + nbase + row) * DIMM + h * HDD + e2) = hv2;
    }
}

// ---------------- launch ----------------
extern "C" void kernel_launch(void* const* d_in, const int* in_sizes, int n_in,
                              void* d_out, int out_size) {
    const float* query = (const float*)d_in[0];
    const float* key   = (const float*)d_in[1];
    const float* value = (const float*)d_in[2];
    const float* Wq = (const float*)d_in[3];
    const float* bq = (const float*)d_in[4];
    const float* Wk = (const float*)d_in[5];
    const float* bk = (const float*)d_in[6];
    const float* Wv = (const float*)d_in[7];
    const float* bv = (const float*)d_in[8];
    const float* Wo = (const float*)d_in[9];
    const float* bo = (const float*)d_in[10];
    const int* mask = (const int*)d_in[11];

    float *KVPp, *KSPp, *KSp;
    __half *hq, *hk, *hv, *Q16, *K16, *V16, *hA, *Wh, *KV16;
    cudaGetSymbolAddress((void**)&hq, g_hq);
    cudaGetSymbolAddress((void**)&hk, g_hk);
    cudaGetSymbolAddress((void**)&hv, g_hv);
    cudaGetSymbolAddress((void**)&Q16, g_Q16);
    cudaGetSymbolAddress((void**)&K16, g_K16);
    cudaGetSymbolAddress((void**)&V16, g_V16);
    cudaGetSymbolAddress((void**)&hA, g_hA);
    cudaGetSymbolAddress((void**)&Wh, g_Wh);
    cudaGetSymbolAddress((void**)&KVPp, g_kvp);
    cudaGetSymbolAddress((void**)&KSPp, g_ksp);
    cudaGetSymbolAddress((void**)&KV16, g_kv16);
    cudaGetSymbolAddress((void**)&KSp, g_ksum);

    cudaFuncSetAttribute(gemm_qkv, cudaFuncAttributeMaxDynamicSharedMemorySize, GEMM_DSMEM);
    cudaFuncSetAttribute(gemm_one, cudaFuncAttributeMaxDynamicSharedMemorySize, GEMM_DSMEM);

    dim3 ggrid3(DIMM / 128, MM / 128, 3);
    dim3 ggrid(DIMM / 128, MM / 128);

    cvt_all<<<dim3(4096, 4), 256>>>(query, key, value, Wq, Wk, Wv, Wo,
                                    hq, hk, hv, Wh);
    gemm_qkv<<<ggrid3, 256, GEMM_DSMEM>>>(hq, hk, hv, Wh, bq, bk, bv, Q16, K16, V16);
    kv_h<<<dim3(KVC, 64), 128>>>(K16, V16, mask, KVPp, KSPp);
    reduce_kv<<<dim3(64, 8), 128>>>(KVPp, KSPp, KV16, KSp);
    attn_h<<<dim3(NN / 128, 64), 128, ATTN_DSMEM>>>(Q16, KV16, KSp, hA);
    gemm_one<<<ggrid, 256, GEMM_DSMEM>>>(hA, Wh + 3 * (size_t)DIMM * DIMM, bo, (float*)d_out);
}